// round 5
// baseline (speedup 1.0000x reference)
#include <cuda_runtime.h>
#include <cstdint>

// WKV (RWKV v4) — single-kernel segmented scan, decoupled lookback,
// self-cleaning flags (no auxiliary zeroing kernel).
//
//   state_t = lam*state_{t-1} + e^{k_t}(v_t, 1),  lam = exp(-exp(td[c]))
//   y_t = (A_{t-1} + e^u e^{k_t} v_t) / (B_{t-1} + e^u e^{k_t})
//
// Work item w = (row, segment); row = (batch, 128-channel tile).
// S_eff = 16 segments of 64 steps: the aggregate live sweep-1 footprint of
// all resident blocks is 1024 * 64*128*2*4B = 64 MiB < L2 (126 MB), so each
// block's sweep-2 re-read of its own segment is served by L2, not DRAM.
// Output stores use .cs (evict-first) so y writes don't displace k/v tiles.
//
// Flag lifecycle (graph-replay safe without re-zeroing):
//   slot j < S_eff-1 publishes local state + flag; it has exactly
//   S_eff-1-j consumers (slots j+1..S_eff-1 of the same row). Each consumer
//   increments g_cnt[wj] after reading; the last one clears flag and count.
//   Slot S_eff-1 never publishes. Net: all flags/counts are zero at kernel
//   end, every launch.

constexpr int CH    = 128;  // channels per block == threads
constexpr int TT    = 8;    // timesteps per smem tile
constexpr int NBUF  = 3;    // cp.async pipeline depth
constexpr int S_MAX = 16;   // max T segments
constexpr int GRID  = 1024;
constexpr int SMEM_BYTES = NBUF * 2 * TT * CH * (int)sizeof(float); // 24 KB

__device__ float    g_A[1 << 19];
__device__ float    g_B[1 << 19];
__device__ unsigned g_flag[4096];
__device__ unsigned g_cnt[4096];

__device__ __forceinline__ void cpasync16(float* s, const float* g) {
    unsigned sa = (unsigned)__cvta_generic_to_shared(s);
    asm volatile("cp.async.cg.shared.global [%0], [%1], 16;\n"
                 :: "r"(sa), "l"(g) : "memory");
}

__device__ __forceinline__ void stcs(float* p, float v) {
    asm volatile("st.global.cs.f32 [%0], %1;\n" :: "l"(p), "f"(v) : "memory");
}

__device__ __forceinline__ int read_dim(const void* p) {
    int i = *reinterpret_cast<const int*>(p);
    if (i >= 1 && i <= (1 << 20)) return i;
    float f = *reinterpret_cast<const float*>(p);
    int fi = (int)f;
    return (fi >= 1) ? fi : 1;
}

template <bool EMIT>
__device__ __forceinline__ void scan_segment(
    float* smem, int tid,
    const float* __restrict__ kbase, const float* __restrict__ vbase,
    float* __restrict__ obase,            // out + b*T*C + c (EMIT only)
    int segstart, int segend, int C, int c0,
    bool valid, bool vec_ok, float lam, float eu,
    float& A, float& Bs)
{
    const int ntiles = (segend - segstart + TT - 1) / TT;

    auto load_tile = [&](int tile) {
        const int buf = tile % NBUF;
        float* sk = smem + (size_t)buf * 2 * TT * CH;
        float* sv = sk + TT * CH;
        const int t0 = segstart + tile * TT;
        if (vec_ok) {
            #pragma unroll
            for (int j = 0; j < TT / 4; ++j) {
                const int q    = tid + j * CH;
                const int row  = q >> 5;
                const int col4 = (q & 31) * 4;
                int gt = t0 + row; if (gt >= segend) gt = segend - 1;
                const int gc = c0 + col4;
                if (gc + 4 <= C) {
                    const long long go = (long long)gt * C + gc;
                    cpasync16(sk + row * CH + col4, kbase + go);
                    cpasync16(sv + row * CH + col4, vbase + go);
                }
            }
        } else {
            for (int r = 0; r < TT; ++r) {
                int gt = t0 + r; if (gt >= segend) gt = segend - 1;
                if (valid) {
                    const long long go = (long long)gt * C + (c0 + tid);
                    sk[r * CH + tid] = kbase[go];
                    sv[r * CH + tid] = vbase[go];
                }
            }
        }
    };

    #pragma unroll
    for (int p = 0; p < NBUF - 1; ++p) {
        if (p < ntiles) load_tile(p);
        asm volatile("cp.async.commit_group;\n" ::);
    }

    for (int tile = 0; tile < ntiles; ++tile) {
        asm volatile("cp.async.wait_group %0;\n" :: "n"(NBUF - 2));
        __syncthreads();

        const int buf = tile % NBUF;
        const float* sk = smem + (size_t)buf * 2 * TT * CH + tid;
        const float* sv = sk + TT * CH;
        const int t0 = segstart + tile * TT;
        const int jmax = min(TT, segend - t0);

        #pragma unroll
        for (int j = 0; j < TT; ++j) {
            if (j < jmax) {
                const float kt = sk[j * CH];
                const float vt = sv[j * CH];
                const float ek = __expf(kt);
                if (EMIT) {
                    const float eku = eu * ek;
                    const float y = __fdividef(fmaf(eku, vt, A), Bs + eku);
                    if (valid)
                        stcs(obase + (long long)(t0 + j) * C, y);
                }
                A  = fmaf(lam, A,  ek * vt);
                Bs = fmaf(lam, Bs, ek);
            }
        }
        __syncthreads();

        const int nt = tile + NBUF - 1;
        if (nt < ntiles) load_tile(nt);
        asm volatile("cp.async.commit_group;\n" ::);
    }
    asm volatile("cp.async.wait_group 0;\n" ::);
    __syncthreads();
}

__global__ __launch_bounds__(CH, 8)
void wkv_lookback_kernel(const void* __restrict__ seqlen_p,
                         const float* __restrict__ td,
                         const float* __restrict__ tf,
                         const float* __restrict__ kg,
                         const float* __restrict__ vg,
                         float* __restrict__ out,
                         int C, long long BTC)
{
    extern __shared__ float smem[];
    const int tid = threadIdx.x;

    const int T = read_dim(seqlen_p);
    const long long BT = BTC / C;
    const int B = (int)(BT / T);
    const int ctiles = (C + CH - 1) / CH;
    const int nrows  = B * ctiles;
    int S_eff = (int)((2 * gridDim.x) / nrows);
    if (S_eff < 1) S_eff = 1;
    if (S_eff > S_MAX) S_eff = S_MAX;
    const int seglen = (T + S_eff - 1) / S_eff;
    const int nwork  = nrows * S_eff;
    const bool vec_ok = ((C & 3) == 0) &&
                        ((((uintptr_t)kg) & 15) == 0) &&
                        ((((uintptr_t)vg) & 15) == 0);

    // Ascending-w processing per block + waits only on strictly lower w +
    // all gridDim blocks resident  ->  deadlock-free.
    for (int w = blockIdx.x; w < nwork; w += gridDim.x) {
        const int s     = w % S_eff;
        const int rowid = w / S_eff;
        const int b     = rowid / ctiles;
        const int c0    = (rowid % ctiles) * CH;
        const int c     = c0 + tid;
        const bool valid = (c < C);

        const int segstart = min(s * seglen, T);
        const int segend   = min(T, segstart + seglen);

        const float ew  = valid ? __expf(td[c]) : 0.f;  // e^{td}
        const float lam = __expf(-ew);                  // exp(-e^{td})

        const float* kbase = kg + (long long)b * T * C;
        const float* vbase = vg + (long long)b * T * C;
        float* obase = out + (long long)b * T * C + c;

        // ---- sweep 1: local scan from zero init ----
        float A = 0.f, Bs = 0.f;
        if (segstart < segend)
            scan_segment<false>(smem, tid, kbase, vbase, nullptr,
                                segstart, segend, C, c0, valid, vec_ok,
                                lam, 0.f, A, Bs);

        // ---- publish local state (only if someone will consume it) ----
        if (s < S_eff - 1) {
            const size_t st = (size_t)w * CH + tid;
            g_A[st] = A;
            g_B[st] = Bs;
            __threadfence();
            __syncthreads();
            if (tid == 0) atomicExch(&g_flag[w], 1u);
        }

        // ---- lookback: fold predecessor locals into seed ----
        float sa = 0.f, sb = 0.f;
        for (int j = 0; j < s; ++j) {
            const int wj = rowid * S_eff + j;
            if (tid == 0) {
                volatile unsigned* f = &g_flag[wj];
                while (*f == 0u) __nanosleep(64);
            }
            __syncthreads();
            int Lj = T - j * seglen;
            Lj = max(0, min(seglen, Lj));
            const float fdec = __expf(-(float)Lj * ew);  // lam^{L_j}
            const size_t st = (size_t)wj * CH + tid;
            sa = fmaf(fdec, sa, __ldcg(&g_A[st]));
            sb = fmaf(fdec, sb, __ldcg(&g_B[st]));
        }
        // Retire consumed flags: last consumer of wj clears it (self-clean
        // so the next graph replay starts from all-zero flags).
        if (s > 0) {
            __syncthreads();           // all threads done reading g_A/g_B
            if (tid == 0) {
                for (int j = 0; j < s; ++j) {
                    const int wj = rowid * S_eff + j;
                    const unsigned need = (unsigned)(S_eff - 1 - j);
                    const unsigned got = atomicAdd(&g_cnt[wj], 1u) + 1u;
                    if (got == need) {
                        g_cnt[wj] = 0u;
                        atomicExch(&g_flag[wj], 0u);
                    }
                }
            }
        }

        // ---- sweep 2: seeded re-scan, emit y (segment L2-hot) ----
        if (segstart < segend) {
            const float eu = valid ? __expf(tf[c]) : 0.f;
            A = sa; Bs = sb;
            scan_segment<true>(smem, tid, kbase, vbase, obase,
                               segstart, segend, C, c0, valid, vec_ok,
                               lam, eu, A, Bs);
        }
    }
}

extern "C" void kernel_launch(void* const* d_in, const int* in_sizes, int n_in,
                              void* d_out, int out_size)
{
    // metadata order: batch_size, seq_len, embedding_dim, time_decay,
    //                 time_first, k, v
    const void*  seqlen_p = d_in[1];
    const float* td = (const float*)d_in[3];
    const float* tf = (const float*)d_in[4];
    const float* k  = (const float*)d_in[5];
    const float* v  = (const float*)d_in[6];
    float* out = (float*)d_out;

    const int C = in_sizes[3];
    const long long BTC = in_sizes[5];

    static bool attr_done = false;
    if (!attr_done) {
        cudaFuncSetAttribute(wkv_lookback_kernel,
                             cudaFuncAttributeMaxDynamicSharedMemorySize,
                             SMEM_BYTES);
        attr_done = true;
    }

    wkv_lookback_kernel<<<GRID, CH, SMEM_BYTES>>>(
        seqlen_p, td, tf, k, v, out, C, BTC);
}

// round 6
// speedup vs baseline: 1.0351x; 1.0351x over previous
#include <cuda_runtime.h>
#include <cstdint>

// WKV (RWKV v4) — single-kernel segmented scan, decoupled lookback.
//
//   state_t = lam*state_{t-1} + e^{k_t}(v_t, 1),  lam = exp(-exp(td[c]))
//   y_t = (A_{t-1} + e^u e^{k_t} v_t) / (B_{t-1} + e^u e^{k_t})
//
// One work item per block (GRID = 2048, S = 16, seglen = 64): at most ~1184
// blocks resident -> live sweep-1 footprint ~76 MiB < L2 (126 MB), so each
// block's sweep-2 re-read of its own segment is L2-hot. Lookback waits only
// on strictly-lower block ids (CUB decoupled-lookback forward progress).
// Output stores are .cs (evict-first) so y never displaces k/v in L2.
//
// Flag lifecycle (graph-replay safe, no zeroing kernel): slot j < S-1 has
// exactly S-1-j consumers; the last consumer clears flag+count, so all
// state is zero again at kernel end.

constexpr int CH    = 128;  // channels per block == threads
constexpr int TT    = 8;    // timesteps per smem tile
constexpr int NBUF  = 3;    // cp.async pipeline depth
constexpr int S_MAX = 16;   // max T segments
constexpr int GRID  = 2048;
constexpr int SMEM_BYTES = NBUF * 2 * TT * CH * (int)sizeof(float); // 24 KB

__device__ float    g_A[1 << 19];
__device__ float    g_B[1 << 19];
__device__ unsigned g_flag[GRID];
__device__ unsigned g_cnt[GRID];

__device__ __forceinline__ void cpasync16(float* s, const float* g) {
    unsigned sa = (unsigned)__cvta_generic_to_shared(s);
    asm volatile("cp.async.cg.shared.global [%0], [%1], 16;\n"
                 :: "r"(sa), "l"(g) : "memory");
}

__device__ __forceinline__ void stcs(float* p, float v) {
    asm volatile("st.global.cs.f32 [%0], %1;\n" :: "l"(p), "f"(v) : "memory");
}

__device__ __forceinline__ int read_dim(const void* p) {
    int i = *reinterpret_cast<const int*>(p);
    if (i >= 1 && i <= (1 << 20)) return i;
    float f = *reinterpret_cast<const float*>(p);
    int fi = (int)f;
    return (fi >= 1) ? fi : 1;
}

template <bool EMIT>
__device__ __forceinline__ void scan_segment(
    float* smem, int tid,
    const float* __restrict__ kbase, const float* __restrict__ vbase,
    float* __restrict__ obase,            // out + b*T*C + c (EMIT only)
    int segstart, int segend, int C, int c0,
    bool valid, bool vec_ok, float lam, float eu,
    float& A, float& Bs)
{
    const int ntiles = (segend - segstart + TT - 1) / TT;

    auto load_tile = [&](int tile) {
        const int buf = tile % NBUF;
        float* sk = smem + (size_t)buf * 2 * TT * CH;
        float* sv = sk + TT * CH;
        const int t0 = segstart + tile * TT;
        if (vec_ok) {
            #pragma unroll
            for (int j = 0; j < TT / 4; ++j) {
                const int q    = tid + j * CH;
                const int row  = q >> 5;
                const int col4 = (q & 31) * 4;
                int gt = t0 + row; if (gt >= segend) gt = segend - 1;
                const int gc = c0 + col4;
                if (gc + 4 <= C) {
                    const long long go = (long long)gt * C + gc;
                    cpasync16(sk + row * CH + col4, kbase + go);
                    cpasync16(sv + row * CH + col4, vbase + go);
                }
            }
        } else {
            for (int r = 0; r < TT; ++r) {
                int gt = t0 + r; if (gt >= segend) gt = segend - 1;
                if (valid) {
                    const long long go = (long long)gt * C + (c0 + tid);
                    sk[r * CH + tid] = kbase[go];
                    sv[r * CH + tid] = vbase[go];
                }
            }
        }
    };

    #pragma unroll
    for (int p = 0; p < NBUF - 1; ++p) {
        if (p < ntiles) load_tile(p);
        asm volatile("cp.async.commit_group;\n" ::);
    }

    for (int tile = 0; tile < ntiles; ++tile) {
        asm volatile("cp.async.wait_group %0;\n" :: "n"(NBUF - 2));
        __syncthreads();

        const int buf = tile % NBUF;
        const float* sk = smem + (size_t)buf * 2 * TT * CH + tid;
        const float* sv = sk + TT * CH;
        const int t0 = segstart + tile * TT;
        const int jmax = min(TT, segend - t0);

        #pragma unroll
        for (int j = 0; j < TT; ++j) {
            if (j < jmax) {
                const float kt = sk[j * CH];
                const float vt = sv[j * CH];
                const float ek = __expf(kt);
                if (EMIT) {
                    const float eku = eu * ek;
                    const float y = __fdividef(fmaf(eku, vt, A), Bs + eku);
                    if (valid)
                        stcs(obase + (long long)(t0 + j) * C, y);
                }
                A  = fmaf(lam, A,  ek * vt);
                Bs = fmaf(lam, Bs, ek);
            }
        }
        __syncthreads();

        const int nt = tile + NBUF - 1;
        if (nt < ntiles) load_tile(nt);
        asm volatile("cp.async.commit_group;\n" ::);
    }
    asm volatile("cp.async.wait_group 0;\n" ::);
    __syncthreads();
}

__global__ __launch_bounds__(CH, 8)
void wkv_lookback_kernel(const void* __restrict__ seqlen_p,
                         const float* __restrict__ td,
                         const float* __restrict__ tf,
                         const float* __restrict__ kg,
                         const float* __restrict__ vg,
                         float* __restrict__ out,
                         int C, long long BTC)
{
    extern __shared__ float smem[];
    const int tid = threadIdx.x;

    const int T = read_dim(seqlen_p);
    const long long BT = BTC / C;
    const int B = (int)(BT / T);
    const int ctiles = (C + CH - 1) / CH;
    const int nrows  = B * ctiles;
    int S_eff = (int)(gridDim.x / nrows);      // one work item per block
    if (S_eff < 1) S_eff = 1;
    if (S_eff > S_MAX) S_eff = S_MAX;
    const int seglen = (T + S_eff - 1) / S_eff;
    const int nwork  = nrows * S_eff;
    const bool vec_ok = ((C & 3) == 0) &&
                        ((((uintptr_t)kg) & 15) == 0) &&
                        ((((uintptr_t)vg) & 15) == 0);

    // Waits target only strictly-lower w (== lower blockIdx since
    // nwork <= gridDim): lower blocks are finished or resident -> progress.
    for (int w = blockIdx.x; w < nwork; w += gridDim.x) {
        const int s     = w % S_eff;
        const int rowid = w / S_eff;
        const int b     = rowid / ctiles;
        const int c0    = (rowid % ctiles) * CH;
        const int c     = c0 + tid;
        const bool valid = (c < C);

        const int segstart = min(s * seglen, T);
        const int segend   = min(T, segstart + seglen);

        const float ew  = valid ? __expf(td[c]) : 0.f;  // e^{td}
        const float lam = __expf(-ew);                  // exp(-e^{td})

        const float* kbase = kg + (long long)b * T * C;
        const float* vbase = vg + (long long)b * T * C;
        float* obase = out + (long long)b * T * C + c;

        // ---- sweep 1: local scan from zero init ----
        float A = 0.f, Bs = 0.f;
        if (segstart < segend)
            scan_segment<false>(smem, tid, kbase, vbase, nullptr,
                                segstart, segend, C, c0, valid, vec_ok,
                                lam, 0.f, A, Bs);

        // ---- publish local state (only if someone will consume it) ----
        if (s < S_eff - 1) {
            const size_t st = (size_t)w * CH + tid;
            g_A[st] = A;
            g_B[st] = Bs;
            __threadfence();
            __syncthreads();
            if (tid == 0) atomicExch(&g_flag[w], 1u);
        }

        // ---- lookback: fold predecessor locals into seed ----
        float sa = 0.f, sb = 0.f;
        for (int j = 0; j < s; ++j) {
            const int wj = rowid * S_eff + j;
            if (tid == 0) {
                volatile unsigned* f = &g_flag[wj];
                while (*f == 0u) __nanosleep(64);
            }
            __syncthreads();
            int Lj = T - j * seglen;
            Lj = max(0, min(seglen, Lj));
            const float fdec = __expf(-(float)Lj * ew);  // lam^{L_j}
            const size_t st = (size_t)wj * CH + tid;
            sa = fmaf(fdec, sa, __ldcg(&g_A[st]));
            sb = fmaf(fdec, sb, __ldcg(&g_B[st]));
        }
        // Retire consumed flags: the last consumer of wj clears it so the
        // next graph replay starts from all-zero state.
        if (s > 0) {
            __syncthreads();           // all threads done reading g_A/g_B
            if (tid == 0) {
                for (int j = 0; j < s; ++j) {
                    const int wj = rowid * S_eff + j;
                    const unsigned need = (unsigned)(S_eff - 1 - j);
                    const unsigned got = atomicAdd(&g_cnt[wj], 1u) + 1u;
                    if (got == need) {
                        g_cnt[wj] = 0u;
                        atomicExch(&g_flag[wj], 0u);
                    }
                }
            }
        }

        // ---- sweep 2: seeded re-scan, emit y (segment L2-hot) ----
        if (segstart < segend) {
            const float eu = valid ? __expf(tf[c]) : 0.f;
            A = sa; Bs = sb;
            scan_segment<true>(smem, tid, kbase, vbase, obase,
                               segstart, segend, C, c0, valid, vec_ok,
                               lam, eu, A, Bs);
        }
    }
}

extern "C" void kernel_launch(void* const* d_in, const int* in_sizes, int n_in,
                              void* d_out, int out_size)
{
    // metadata order: batch_size, seq_len, embedding_dim, time_decay,
    //                 time_first, k, v
    const void*  seqlen_p = d_in[1];
    const float* td = (const float*)d_in[3];
    const float* tf = (const float*)d_in[4];
    const float* k  = (const float*)d_in[5];
    const float* v  = (const float*)d_in[6];
    float* out = (float*)d_out;

    const int C = in_sizes[3];
    const long long BTC = in_sizes[5];

    static bool attr_done = false;
    if (!attr_done) {
        cudaFuncSetAttribute(wkv_lookback_kernel,
                             cudaFuncAttributeMaxDynamicSharedMemorySize,
                             SMEM_BYTES);
        attr_done = true;
    }

    wkv_lookback_kernel<<<GRID, CH, SMEM_BYTES>>>(
        seqlen_p, td, tf, k, v, out, C, BTC);
}

// round 7
// speedup vs baseline: 1.0632x; 1.0272x over previous
#include <cuda_runtime.h>
#include <cstdint>

// WKV (RWKV v4) — single-kernel segmented scan, decoupled lookback,
// low-overhead synchronization.
//
//   state_t = lam*state_{t-1} + e^{k_t}(v_t, 1),  lam = exp(-exp(td[c]))
//   y_t = (A_{t-1} + e^u e^{k_t} v_t) / (B_{t-1} + e^u e^{k_t})
//
// GRID=2048, S=16 (seglen 64): resident-block sweep-1 footprint < L2, so
// sweep-2 re-reads its own segment from L2 (R5/R6 confirmed ~192MB total
// DRAM traffic). This round removes the sync overhead that capped the rate:
//  - lookback spin is warp-level (lane0 polls ALL flags, no __syncthreads)
//  - consumer-retire atomics moved AFTER sweep 2 (off critical path)
//  - sweep-2 cp.async prologue issued BEFORE the lookback wait (overlap)
//  - segment 0 emits directly in sweep 1 (no lookback / re-read at all)
// Flags self-clean (slot j has S-1-j consumers; last one resets) so state
// is all-zero at kernel end -> graph-replay safe without a zeroing pass.

constexpr int CH    = 128;  // channels per block == threads
constexpr int TT    = 8;    // timesteps per smem tile
constexpr int NBUF  = 3;    // cp.async pipeline depth
constexpr int S_MAX = 16;   // max T segments
constexpr int GRID  = 2048;
constexpr int SMEM_BYTES = NBUF * 2 * TT * CH * (int)sizeof(float); // 24 KB

__device__ float    g_A[1 << 18];
__device__ float    g_B[1 << 18];
__device__ unsigned g_flag[GRID];
__device__ unsigned g_cnt[GRID];

__device__ __forceinline__ void cpasync16(float* s, const float* g) {
    unsigned sa = (unsigned)__cvta_generic_to_shared(s);
    asm volatile("cp.async.cg.shared.global [%0], [%1], 16;\n"
                 :: "r"(sa), "l"(g) : "memory");
}

__device__ __forceinline__ void stcs(float* p, float v) {
    asm volatile("st.global.cs.f32 [%0], %1;\n" :: "l"(p), "f"(v) : "memory");
}

__device__ __forceinline__ unsigned ld_flag(const unsigned* p) {
    unsigned v;
    asm volatile("ld.global.cg.b32 %0, [%1];\n" : "=r"(v) : "l"(p) : "memory");
    return v;
}

__device__ __forceinline__ int read_dim(const void* p) {
    int i = *reinterpret_cast<const int*>(p);
    if (i >= 1 && i <= (1 << 20)) return i;
    float f = *reinterpret_cast<const float*>(p);
    int fi = (int)f;
    return (fi >= 1) ? fi : 1;
}

struct SegCtx {
    const float* kbase;
    const float* vbase;
    int segstart, segend, C, c0;
    bool valid, vec_ok;
};

__device__ __forceinline__ void load_tile(float* smem, int tid,
                                          const SegCtx& cx, int tile)
{
    const int buf = tile % NBUF;
    float* sk = smem + (size_t)buf * 2 * TT * CH;
    float* sv = sk + TT * CH;
    const int t0 = cx.segstart + tile * TT;
    if (cx.vec_ok) {
        #pragma unroll
        for (int j = 0; j < TT / 4; ++j) {
            const int q    = tid + j * CH;
            const int row  = q >> 5;
            const int col4 = (q & 31) * 4;
            int gt = t0 + row; if (gt >= cx.segend) gt = cx.segend - 1;
            const int gc = cx.c0 + col4;
            if (gc + 4 <= cx.C) {
                const long long go = (long long)gt * cx.C + gc;
                cpasync16(sk + row * CH + col4, cx.kbase + go);
                cpasync16(sv + row * CH + col4, cx.vbase + go);
            }
        }
    } else {
        for (int r = 0; r < TT; ++r) {
            int gt = t0 + r; if (gt >= cx.segend) gt = cx.segend - 1;
            if (cx.valid) {
                const long long go = (long long)gt * cx.C + (cx.c0 + tid);
                sk[r * CH + tid] = cx.kbase[go];
                sv[r * CH + tid] = cx.vbase[go];
            }
        }
    }
}

__device__ __forceinline__ void prefetch_prologue(float* smem, int tid,
                                                  const SegCtx& cx)
{
    const int ntiles = (cx.segend - cx.segstart + TT - 1) / TT;
    #pragma unroll
    for (int p = 0; p < NBUF - 1; ++p) {
        if (p < ntiles) load_tile(smem, tid, cx, p);
        asm volatile("cp.async.commit_group;\n" ::);
    }
}

template <bool EMIT, bool PRE>
__device__ __forceinline__ void scan_segment(
    float* smem, int tid, const SegCtx& cx,
    float* __restrict__ obase,            // out + b*T*C + c (EMIT only)
    float lam, float eu, float& A, float& Bs)
{
    const int ntiles = (cx.segend - cx.segstart + TT - 1) / TT;

    if (!PRE)
        prefetch_prologue(smem, tid, cx);

    for (int tile = 0; tile < ntiles; ++tile) {
        asm volatile("cp.async.wait_group %0;\n" :: "n"(NBUF - 2));
        __syncthreads();

        const int buf = tile % NBUF;
        const float* sk = smem + (size_t)buf * 2 * TT * CH + tid;
        const float* sv = sk + TT * CH;
        const int t0 = cx.segstart + tile * TT;
        const int jmax = min(TT, cx.segend - t0);

        #pragma unroll
        for (int j = 0; j < TT; ++j) {
            if (j < jmax) {
                const float kt = sk[j * CH];
                const float vt = sv[j * CH];
                const float ek = __expf(kt);
                if (EMIT) {
                    const float eku = eu * ek;
                    const float y = __fdividef(fmaf(eku, vt, A), Bs + eku);
                    if (cx.valid)
                        stcs(obase + (long long)(t0 + j) * cx.C, y);
                }
                A  = fmaf(lam, A,  ek * vt);
                Bs = fmaf(lam, Bs, ek);
            }
        }
        __syncthreads();

        const int nt = tile + NBUF - 1;
        if (nt < ntiles) load_tile(smem, tid, cx, nt);
        asm volatile("cp.async.commit_group;\n" ::);
    }
    asm volatile("cp.async.wait_group 0;\n" ::);
    __syncthreads();
}

__global__ __launch_bounds__(CH, 8)
void wkv_lookback_kernel(const void* __restrict__ seqlen_p,
                         const float* __restrict__ td,
                         const float* __restrict__ tf,
                         const float* __restrict__ kg,
                         const float* __restrict__ vg,
                         float* __restrict__ out,
                         int C, long long BTC)
{
    extern __shared__ float smem[];
    const int tid = threadIdx.x;
    const int lane = tid & 31;

    const int T = read_dim(seqlen_p);
    const long long BT = BTC / C;
    const int B = (int)(BT / T);
    const int ctiles = (C + CH - 1) / CH;
    const int nrows  = B * ctiles;
    int S_eff = (int)(gridDim.x / nrows);      // one work item per block
    if (S_eff < 1) S_eff = 1;
    if (S_eff > S_MAX) S_eff = S_MAX;
    const int seglen = (T + S_eff - 1) / S_eff;
    const int nwork  = nrows * S_eff;
    const bool vec_ok = ((C & 3) == 0) &&
                        ((((uintptr_t)kg) & 15) == 0) &&
                        ((((uintptr_t)vg) & 15) == 0);

    // Waits target only strictly-lower work ids -> forward progress with
    // any residency (CUB decoupled-lookback argument).
    for (int w = blockIdx.x; w < nwork; w += gridDim.x) {
        const int s     = w % S_eff;
        const int rowid = w / S_eff;
        const int b     = rowid / ctiles;
        const int c0    = (rowid % ctiles) * CH;
        const int c     = c0 + tid;
        const bool valid = (c < C);

        SegCtx cx;
        cx.kbase = kg + (long long)b * T * C;
        cx.vbase = vg + (long long)b * T * C;
        cx.segstart = min(s * seglen, T);
        cx.segend   = min(T, cx.segstart + seglen);
        cx.C = C; cx.c0 = c0; cx.valid = valid; cx.vec_ok = vec_ok;
        float* obase = out + (long long)b * T * C + c;

        if (cx.segstart >= cx.segend) continue;

        const float ew  = valid ? __expf(td[c]) : 0.f;  // e^{td}
        const float lam = __expf(-ew);                  // exp(-e^{td})
        const float eu  = valid ? __expf(tf[c]) : 0.f;

        float A = 0.f, Bs = 0.f;

        if (s == 0) {
            // Segment 0 needs no seed: emit directly in a single sweep.
            scan_segment<true, false>(smem, tid, cx, obase, lam, eu, A, Bs);
            if (S_eff > 1) {
                const size_t st = (size_t)w * CH + tid;
                __stcg(&g_A[st], A);
                __stcg(&g_B[st], Bs);
                __threadfence();
                __syncthreads();
                if (tid == 0) atomicExch(&g_flag[w], 1u);
            }
            continue;
        }

        // ---- sweep 1: local scan from zero init ----
        scan_segment<false, false>(smem, tid, cx, nullptr, lam, 0.f, A, Bs);

        // ---- publish local state (only if someone will consume it) ----
        if (s < S_eff - 1) {
            const size_t st = (size_t)w * CH + tid;
            __stcg(&g_A[st], A);
            __stcg(&g_B[st], Bs);
            __threadfence();
            __syncthreads();
            if (tid == 0) atomicExch(&g_flag[w], 1u);
        }

        // ---- overlap: issue sweep-2's first tiles before the wait ----
        prefetch_prologue(smem, tid, cx);

        // ---- lookback: warp-level wait, then fold predecessor locals ----
        if (lane == 0) {
            for (int j = 0; j < s; ++j) {
                const unsigned* f = &g_flag[rowid * S_eff + j];
                while (ld_flag(f) == 0u) __nanosleep(64);
            }
        }
        __syncwarp();

        float sa = 0.f, sb = 0.f;
        #pragma unroll 4
        for (int j = 0; j < s; ++j) {
            int Lj = T - j * seglen;
            Lj = max(0, min(seglen, Lj));
            const float fdec = __expf(-(float)Lj * ew);  // lam^{L_j}
            const size_t st = (size_t)(rowid * S_eff + j) * CH + tid;
            sa = fmaf(fdec, sa, __ldcg(&g_A[st]));
            sb = fmaf(fdec, sb, __ldcg(&g_B[st]));
        }

        // ---- sweep 2: seeded re-scan, emit y (segment L2-hot) ----
        A = sa; Bs = sb;
        scan_segment<true, true>(smem, tid, cx, obase, lam, eu, A, Bs);

        // ---- retire consumed flags (off critical path). Last consumer of
        // slot j clears it so the next graph replay starts all-zero. ----
        __syncthreads();               // all threads done reading g_A/g_B
        if (tid == 0) {
            for (int j = 0; j < s; ++j) {
                const int wj = rowid * S_eff + j;
                const unsigned need = (unsigned)(S_eff - 1 - j);
                const unsigned got = atomicAdd(&g_cnt[wj], 1u) + 1u;
                if (got == need) {
                    g_cnt[wj] = 0u;
                    atomicExch(&g_flag[wj], 0u);
                }
            }
        }
    }
}

extern "C" void kernel_launch(void* const* d_in, const int* in_sizes, int n_in,
                              void* d_out, int out_size)
{
    // metadata order: batch_size, seq_len, embedding_dim, time_decay,
    //                 time_first, k, v
    const void*  seqlen_p = d_in[1];
    const float* td = (const float*)d_in[3];
    const float* tf = (const float*)d_in[4];
    const float* k  = (const float*)d_in[5];
    const float* v  = (const float*)d_in[6];
    float* out = (float*)d_out;

    const int C = in_sizes[3];
    const long long BTC = in_sizes[5];

    static bool attr_done = false;
    if (!attr_done) {
        cudaFuncSetAttribute(wkv_lookback_kernel,
                             cudaFuncAttributeMaxDynamicSharedMemorySize,
                             SMEM_BYTES);
        attr_done = true;
    }

    wkv_lookback_kernel<<<GRID, CH, SMEM_BYTES>>>(
        seqlen_p, td, tf, k, v, out, C, BTC);
}